// round 9
// baseline (speedup 1.0000x reference)
#include <cuda_runtime.h>
#include <cuda_bf16.h>
#include <math.h>
#include <stdint.h>

// Problem constants
#define BB    8
#define CC    384
#define C3    1152
#define HH    128
#define WW    128
#define NPIX  16384
#define HEADS 8
#define CH    48
#define TOPK_ 7
#define NCHUNK  16
#define CHUNK_N 1024
#define KDIM  384
#define KCHUNKS 6          // 384 / 64
#define GPERS 148          // persistent grid size

#define SMEM_SWIZZLE_128B(o) ((o) ^ (((o) >> 3) & 0x70))

// ---------------- scratch ---------------------------------------------------
__device__ float g_qkv[(long)BB * C3 * NPIX];
__device__ float g_dw [(long)BB * C3 * NPIX];     // only q,k region used
__device__ float g_norm[BB * 2 * CC];
__device__ float g_Spart[(long)NCHUNK * BB * HEADS * CH * CH];
__device__ float g_attn[BB * HEADS * CH * CH];
__device__ float g_M[BB * CC * CC];
// bf16 split operands, [k][n] layout (n contiguous, row stride NPIX)
__device__ __nv_bfloat16 g_xT0[(long)BB * CC * NPIX];
__device__ __nv_bfloat16 g_xT1[(long)BB * CC * NPIX];
__device__ __nv_bfloat16 g_xT2[(long)BB * CC * NPIX];
__device__ __nv_bfloat16 g_vT0[(long)BB * CC * NPIX];
__device__ __nv_bfloat16 g_vT1[(long)BB * CC * NPIX];
__device__ __nv_bfloat16 g_wq0[C3 * KDIM];
__device__ __nv_bfloat16 g_wq1[C3 * KDIM];
__device__ __nv_bfloat16 g_wq2[C3 * KDIM];
__device__ __nv_bfloat16 g_ma0[BB * CC * CC];
__device__ __nv_bfloat16 g_ma1[BB * CC * CC];

// ---------------- PTX helpers (base sm_103-compatible only) -----------------
__device__ __forceinline__ uint32_t smem_u32(const void* p) {
    uint32_t a;
    asm("{ .reg .u64 t; cvta.to.shared.u64 t, %1; cvt.u32.u64 %0, t; }"
        : "=r"(a) : "l"(p));
    return a;
}

#define CP_ASYNC16(dst, src) \
    asm volatile("cp.async.cg.shared.global [%0], [%1], 16;" :: "r"(dst), "l"(src))
#define CP_COMMIT()  asm volatile("cp.async.commit_group;")
#define CP_WAIT1()   asm volatile("cp.async.wait_group 1;")

#define LDSM_X4(r0, r1, r2, r3, addr) \
    asm volatile("ldmatrix.sync.aligned.m8n8.x4.shared.b16 {%0,%1,%2,%3}, [%4];" \
        : "=r"(r0), "=r"(r1), "=r"(r2), "=r"(r3) : "r"(addr))

#define LDSM_X4_T(r0, r1, r2, r3, addr) \
    asm volatile("ldmatrix.sync.aligned.m8n8.x4.trans.shared.b16 {%0,%1,%2,%3}, [%4];" \
        : "=r"(r0), "=r"(r1), "=r"(r2), "=r"(r3) : "r"(addr))

#define MMA16816(d, a, b0, b1) \
    asm volatile("mma.sync.aligned.m16n8k16.row.col.f32.bf16.bf16.f32 " \
        "{%0,%1,%2,%3}, {%4,%5,%6,%7}, {%8,%9}, {%0,%1,%2,%3};" \
        : "+f"((d)[0]), "+f"((d)[1]), "+f"((d)[2]), "+f"((d)[3]) \
        : "r"((a)[0]), "r"((a)[1]), "r"((a)[2]), "r"((a)[3]), "r"(b0), "r"(b1))

// ---------------- persistent HMMA split-bf16 GEMM ----------------------------
// D[m,n] = sum_k A[m,k]*B[k,n]. A: [m][k] rows (stride KDIM). B: [k][n] rows
// (stride NPIX). CTA tile 128x128, 8 warps of 64x32, flattened (tile,chunk)
// software pipeline: next tile's loads issue before current tile's epilogue.
template<int NSPLIT>
__global__ __launch_bounds__(256, 1)
void gemm_hmma(const __nv_bfloat16* __restrict__ A0, const __nv_bfloat16* __restrict__ A1,
               const __nv_bfloat16* __restrict__ A2,
               const __nv_bfloat16* __restrict__ B0, const __nv_bfloat16* __restrict__ B1,
               const __nv_bfloat16* __restrict__ B2,
               float* __restrict__ C,
               long aBatch, long bBatch, long cBatch,
               int mt, int nt, int ntiles)
{
    constexpr int NTILES = 2 * NSPLIT;
    constexpr int BUFB   = NTILES * 16384;
    extern __shared__ char smem[];
    const uint32_t sb = smem_u32(smem);
    const int tid  = threadIdx.x;
    const int wid  = tid >> 5, lane = tid & 31;
    const int bid  = blockIdx.x;
    const int warp_m = (wid >> 2) * 64, warp_n = (wid & 3) * 32;

    const int myTiles = (ntiles - bid + GPERS - 1) / GPERS;   // ceil((ntiles-bid)/G)
    if (myTiles <= 0) return;
    const int S = myTiles * KCHUNKS;

    uint32_t aoff[4][4];
    {
        const int arow = lane & 15, akh = lane >> 4;
#pragma unroll
        for (int ks = 0; ks < 4; ks++)
#pragma unroll
            for (int i = 0; i < 4; i++) {
                int o = (warp_m + i * 16 + arow) * 128 + (ks * 16 + akh * 8) * 2;
                aoff[i][ks] = SMEM_SWIZZLE_128B(o);
            }
    }
    uint32_t boff[2];
    {
        const int krow = (lane & 7) + (((lane >> 3) & 1) << 3);
        const int ncol = warp_n + ((lane >> 4) << 3);
        boff[0] = (uint32_t)((krow * 256 + ncol * 2) ^ ((krow & 7) << 4));
        boff[1] = (uint32_t)((krow * 256 + (ncol + 16) * 2) ^ ((krow & 7) << 4));
    }

    float acc[4][4][4];
#pragma unroll
    for (int i = 0; i < 4; i++)
#pragma unroll
        for (int j = 0; j < 4; j++)
#pragma unroll
            for (int r = 0; r < 4; r++) acc[i][j][r] = 0.f;

    // Issue loads for flattened step sj into buffer buf.
    auto load_step = [&](int sj, int buf) {
        const int jt  = sj / KCHUNKS;
        const int c   = sj - jt * KCHUNKS;
        const int lin = bid + GPERS * jt;
        const int m0  = (lin % mt) * 128;
        const int t2  = lin / mt;
        const int n0  = (t2 % nt) * 128;
        const int bz  = t2 / nt;
        const int kOff = c * 64;
        const __nv_bfloat16* ta[3];
        ta[0] = A0 + bz * aBatch + (long)m0 * KDIM;
        ta[1] = A1 + bz * aBatch + (long)m0 * KDIM;
        ta[2] = A2 + bz * aBatch + (long)m0 * KDIM;
        const __nv_bfloat16* tb[3];
        tb[0] = B0 + bz * bBatch + n0;
        tb[1] = B1 + bz * bBatch + n0;
        tb[2] = B2 + bz * bBatch + n0;
        const uint32_t bufOff = sb + buf * BUFB;
#pragma unroll
        for (int i = 0; i < NTILES * 4; i++) {
            const int t = tid + i * 256;
            const int tile = t >> 10;
            const int idx  = t & 1023;
            const __nv_bfloat16* gp;
            uint32_t so;
            if (tile < NSPLIT) {              // A: 128m x 64k, 128B rows
                const int r = idx >> 3, s8 = idx & 7;
                gp = ta[tile] + (long)r * KDIM + kOff + s8 * 8;
                so = bufOff + tile * 16384 + SMEM_SWIZZLE_128B(r * 128 + s8 * 16);
            } else {                          // B: 64k x 128n, 256B rows
                const int r = idx >> 4, s8 = idx & 15;
                gp = tb[tile - NSPLIT] + (long)(kOff + r) * NPIX + s8 * 8;
                so = bufOff + tile * 16384 + ((r * 256 + s8 * 16) ^ ((r & 7) << 4));
            }
            CP_ASYNC16(so, gp);
        }
    };

    load_step(0, 0); CP_COMMIT();
    if (S > 1) load_step(1, 1);
    CP_COMMIT();

    for (int s = 0; s < S; s++) {
        CP_WAIT1();
        __syncthreads();
        const uint32_t bufA = sb + (s & 1) * BUFB;
#pragma unroll
        for (int ks = 0; ks < 4; ks++) {
            uint32_t a[NSPLIT][4][4], b[NSPLIT][2][4];
#pragma unroll
            for (int ai = 0; ai < NSPLIT; ai++) {
                const uint32_t At = bufA + ai * 16384;
#pragma unroll
                for (int i = 0; i < 4; i++)
                    LDSM_X4(a[ai][i][0], a[ai][i][1], a[ai][i][2], a[ai][i][3],
                            At + aoff[i][ks]);
            }
#pragma unroll
            for (int bi = 0; bi < NSPLIT; bi++) {
                const uint32_t Bt = bufA + (NSPLIT + bi) * 16384 + ks * 4096;
#pragma unroll
                for (int q = 0; q < 2; q++)
                    LDSM_X4_T(b[bi][q][0], b[bi][q][1], b[bi][q][2], b[bi][q][3],
                              Bt + boff[q]);
            }
#pragma unroll
            for (int ai = 0; ai < NSPLIT; ai++)
#pragma unroll
                for (int bi = 0; bi < NSPLIT; bi++) {
                    if (ai + bi >= NSPLIT) continue;
#pragma unroll
                    for (int i = 0; i < 4; i++)
#pragma unroll
                        for (int j = 0; j < 4; j++)
                            MMA16816(acc[i][j], a[ai][i],
                                     b[bi][j >> 1][(j & 1) * 2],
                                     b[bi][j >> 1][(j & 1) * 2 + 1]);
                }
        }
        __syncthreads();
        if (s + 2 < S) load_step(s + 2, s & 1);
        CP_COMMIT();

        if ((s % KCHUNKS) == KCHUNKS - 1) {
            // epilogue for tile s/KCHUNKS (overlaps the loads just issued)
            const int lin = bid + GPERS * (s / KCHUNKS);
            const int m0  = (lin % mt) * 128;
            const int t2  = lin / mt;
            const int n0  = (t2 % nt) * 128;
            const int bz  = t2 / nt;
            const int gid = lane >> 2, qd = lane & 3;
#pragma unroll
            for (int i = 0; i < 4; i++) {
                const int r0 = m0 + warp_m + i * 16 + gid;
                float* p0 = C + bz * cBatch + (long)r0 * NPIX + n0 + warp_n + qd * 2;
                float* p1 = p0 + 8L * NPIX;
#pragma unroll
                for (int j = 0; j < 4; j++) {
                    *(float2*)(p0 + j * 8) = make_float2(acc[i][j][0], acc[i][j][1]);
                    *(float2*)(p1 + j * 8) = make_float2(acc[i][j][2], acc[i][j][3]);
                    acc[i][j][0] = acc[i][j][1] = acc[i][j][2] = acc[i][j][3] = 0.f;
                }
            }
        }
    }
}

// ---------------- vectorized elementwise bf16 split (4 elems/thread) --------
template<int NSPLIT>
__global__ void convert_split(const float* __restrict__ in, long n,
                              __nv_bfloat16* __restrict__ o0,
                              __nv_bfloat16* __restrict__ o1,
                              __nv_bfloat16* __restrict__ o2)
{
    long i = ((long)blockIdx.x * blockDim.x + threadIdx.x) * 4;
    if (i >= n) return;
    float4 v = *(const float4*)(in + i);
    float vv[4] = {v.x, v.y, v.z, v.w};
    __nv_bfloat16 h0[4], h1[4], h2[4];
#pragma unroll
    for (int j = 0; j < 4; j++) {
        h0[j] = __float2bfloat16(vv[j]);
        float r1 = vv[j] - __bfloat162float(h0[j]);
        h1[j] = __float2bfloat16(r1);
        if (NSPLIT == 3) {
            float r2 = r1 - __bfloat162float(h1[j]);
            h2[j] = __float2bfloat16(r2);
        }
    }
    *(uint2*)(o0 + i) = *(uint2*)h0;
    *(uint2*)(o1 + i) = *(uint2*)h1;
    if (NSPLIT == 3) *(uint2*)(o2 + i) = *(uint2*)h2;
}

// ---------------- zero norm accumulator -------------------------------------
__global__ void zero_norm(float* __restrict__ nrm)
{
    int i = blockIdx.x * 256 + threadIdx.x;
    if (i < BB * 2 * CC) nrm[i] = 0.f;
}

// ---------------- fused depthwise 3x3 + norms + v bf16 split ----------------
__global__ __launch_bounds__(256)
void dwconv3x3_fused(const float* __restrict__ in,
                     const float* __restrict__ w,
                     float* __restrict__ out,
                     float* __restrict__ nrmsq,
                     __nv_bfloat16* __restrict__ vT0,
                     __nv_bfloat16* __restrict__ vT1)
{
    const int ch = blockIdx.y;                 // 0 .. BB*C3-1
    const int c  = ch % C3;
    const int b  = ch / C3;
    const int y0 = blockIdx.x * 8;
    const float* ip = in + (long)ch * NPIX;

    __shared__ float s[10][136];

    const int tid = threadIdx.x;
    const int r   = tid >> 5;
    const int l   = tid & 31;

#pragma unroll
    for (int j = r; j < 10; j += 8) {
        const int gy = y0 - 1 + j;
        float4 v = make_float4(0.f, 0.f, 0.f, 0.f);
        if (gy >= 0 && gy < HH) v = *(const float4*)(ip + gy * WW + l * 4);
        *(float4*)&s[j][4 + l * 4] = v;
        if (l == 0)  s[j][3]   = 0.f;
        if (l == 31) s[j][132] = 0.f;
    }

    float wv[9];
#pragma unroll
    for (int i = 0; i < 9; i++) wv[i] = w[c * 9 + i];
    __syncthreads();

    const int rseg = r >> 2;
    const int cseg = r & 3;
    const int col  = cseg * 32 + l;
    const int rb   = rseg * 4;

    float o[4] = {0.f, 0.f, 0.f, 0.f};
#pragma unroll
    for (int j = 0; j < 6; j++) {
        const float m0 = s[rb + j][3 + col];
        const float m1 = s[rb + j][4 + col];
        const float m2 = s[rb + j][5 + col];
#pragma unroll
        for (int i = 0; i < 4; i++) {
            const int d = j - i;
            if (d >= 0 && d < 3)
                o[i] += wv[d * 3 + 0] * m0 + wv[d * 3 + 1] * m1 + wv[d * 3 + 2] * m2;
        }
    }

    if (c < 2 * CC) {
        float* op = out + (long)ch * NPIX;
        float ss = 0.f;
#pragma unroll
        for (int i = 0; i < 4; i++) {
            op[(y0 + rseg * 4 + i) * WW + col] = o[i];
            ss += o[i] * o[i];
        }
#pragma unroll
        for (int off = 16; off > 0; off >>= 1)
            ss += __shfl_xor_sync(0xFFFFFFFFu, ss, off);
        if (l == 0) atomicAdd(&nrmsq[b * (2 * CC) + c], ss);
    } else {
        const long base = ((long)b * CC + (c - 2 * CC)) * NPIX;
#pragma unroll
        for (int i = 0; i < 4; i++) {
            const int pix = (y0 + rseg * 4 + i) * WW + col;
            const float v = o[i];
            __nv_bfloat16 h = __float2bfloat16(v);
            vT0[base + pix] = h;
            vT1[base + pix] = __float2bfloat16(v - __bfloat162float(h));
        }
    }
}

// ---------------- gram partials v2: 64 threads, 6x6 register tile -----------
__global__ __launch_bounds__(64)
void gram_partial(const float* __restrict__ dw, float* __restrict__ spart)
{
    const int bh    = blockIdx.x;
    const int chunk = blockIdx.y;
    const int b = bh / HEADS, h = bh % HEADS;

    const float* qbase = dw + ((long)b * C3 + h * CH) * NPIX + chunk * CHUNK_N;
    const float* kbase = dw + ((long)b * C3 + CC + h * CH) * NPIX + chunk * CHUNK_N;

    __shared__ float qs[CH][68];
    __shared__ float ks[CH][68];

    float acc[6][6];
#pragma unroll
    for (int i = 0; i < 6; i++)
#pragma unroll
        for (int j = 0; j < 6; j++) acc[i][j] = 0.f;

    const int tid = threadIdx.x;
    const int ti  = tid >> 3, tj = tid & 7;    // 8x8 thread grid

    for (int nn = 0; nn < CHUNK_N; nn += 64) {
#pragma unroll
        for (int l = 0; l < 12; l++) {
            int idx  = tid + l * 64;
            int row  = idx >> 4;
            int col4 = (idx & 15) * 4;
            *(float4*)&qs[row][col4] = *(const float4*)(qbase + (long)row * NPIX + nn + col4);
            *(float4*)&ks[row][col4] = *(const float4*)(kbase + (long)row * NPIX + nn + col4);
        }
        __syncthreads();
#pragma unroll 2
        for (int k = 0; k < 64; k += 2) {
            float2 rq[6], rk[6];
#pragma unroll
            for (int i = 0; i < 6; i++) rq[i] = *(const float2*)&qs[ti + 8 * i][k];
#pragma unroll
            for (int j = 0; j < 6; j++) rk[j] = *(const float2*)&ks[tj + 8 * j][k];
#pragma unroll
            for (int i = 0; i < 6; i++)
#pragma unroll
                for (int j = 0; j < 6; j++)
                    acc[i][j] += rq[i].x * rk[j].x + rq[i].y * rk[j].y;
        }
        __syncthreads();
    }

    float* sp = spart + ((long)chunk * (BB * HEADS) + bh) * (CH * CH);
#pragma unroll
    for (int i = 0; i < 6; i++)
#pragma unroll
        for (int j = 0; j < 6; j++)
            sp[(ti + 8 * i) * CH + (tj + 8 * j)] = acc[i][j];
}

// ---------------- top-7 + masked softmax ------------------------------------
__global__ void topk_softmax(const float* __restrict__ spart,
                             const float* __restrict__ nrmsq,
                             const float* __restrict__ temp,
                             float* __restrict__ attn)
{
    const int row = blockIdx.x * blockDim.x + threadIdx.x;
    if (row >= BB * HEADS * CH) return;
    const int c  = row % CH;
    const int bh = row / CH;
    const int h  = bh % HEADS, b = bh / HEADS;

    const float nq = fmaxf(sqrtf(nrmsq[b * 768 + h * CH + c]), 1e-12f);
    const float t  = temp[h];

    float w[CH];
    for (int d = 0; d < CH; d++) {
        float s = 0.f;
        for (int ck = 0; ck < NCHUNK; ck++)
            s += spart[((long)ck * (BB * HEADS) + bh) * (CH * CH) + c * CH + d];
        const float nk = fmaxf(sqrtf(nrmsq[b * 768 + CC + h * CH + d]), 1e-12f);
        w[d] = s / (nq * nk) * t;
    }

    bool sel[CH];
    for (int d = 0; d < CH; d++) sel[d] = false;
    float m = -INFINITY;
    for (int it = 0; it < TOPK_; it++) {
        int bi = 0; float bv = -INFINITY;
        for (int d = 0; d < CH; d++)
            if (!sel[d] && w[d] > bv) { bv = w[d]; bi = d; }
        sel[bi] = true;
        if (it == 0) m = bv;
    }

    float ssum = 0.f;
    float e[CH];
    for (int d = 0; d < CH; d++) {
        e[d] = sel[d] ? expf(w[d] - m) : 0.f;
        ssum += e[d];
    }
    const float inv = 1.f / ssum;
    float* ap = attn + ((long)bh * CH + c) * CH;
    for (int d = 0; d < CH; d++) ap[d] = e[d] * inv;
}

// ---------------- fold proj into attn ---------------------------------------
__global__ __launch_bounds__(256)
void combine_proj(const float* __restrict__ attn,
                  const float* __restrict__ projw,
                  float* __restrict__ Mo)
{
    const int bh = blockIdx.x;
    const int ot = blockIdx.y;
    const int b = bh / HEADS, h = bh % HEADS;

    __shared__ float as[CH][CH + 1];
    for (int l = threadIdx.x; l < CH * CH; l += 256)
        as[l / CH][l % CH] = attn[(long)bh * CH * CH + l];
    __syncthreads();

    for (int l = threadIdx.x; l < 128 * CH; l += 256) {
        const int ol = l / CH, d = l % CH;
        const int o  = ot * 128 + ol;
        const float* pw = projw + (long)o * CC + h * CH;
        float s = 0.f;
#pragma unroll
        for (int cc = 0; cc < CH; cc++) s += pw[cc] * as[cc][d];
        Mo[((long)b * CC + o) * CC + h * CH + d] = s;
    }
}

// ---------------- launcher ---------------------------------------------------
extern "C" void kernel_launch(void* const* d_in, const int* in_sizes, int n_in,
                              void* d_out, int out_size)
{
    const float* x     = (const float*)d_in[0];
    const float* qkv_w = (const float*)d_in[1];
    const float* dw_w  = (const float*)d_in[2];
    const float* projw = (const float*)d_in[3];
    const float* temp  = (const float*)d_in[4];
    float* out = (float*)d_out;

    float *qkv, *dw, *nrm, *spart, *attn, *Mm;
    cudaGetSymbolAddress((void**)&qkv,   g_qkv);
    cudaGetSymbolAddress((void**)&dw,    g_dw);
    cudaGetSymbolAddress((void**)&nrm,   g_norm);
    cudaGetSymbolAddress((void**)&spart, g_Spart);
    cudaGetSymbolAddress((void**)&attn,  g_attn);
    cudaGetSymbolAddress((void**)&Mm,    g_M);

    __nv_bfloat16 *xT0, *xT1, *xT2, *vT0, *vT1, *wq0, *wq1, *wq2, *ma0, *ma1;
    cudaGetSymbolAddress((void**)&xT0, g_xT0);
    cudaGetSymbolAddress((void**)&xT1, g_xT1);
    cudaGetSymbolAddress((void**)&xT2, g_xT2);
    cudaGetSymbolAddress((void**)&vT0, g_vT0);
    cudaGetSymbolAddress((void**)&vT1, g_vT1);
    cudaGetSymbolAddress((void**)&wq0, g_wq0);
    cudaGetSymbolAddress((void**)&wq1, g_wq1);
    cudaGetSymbolAddress((void**)&wq2, g_wq2);
    cudaGetSymbolAddress((void**)&ma0, g_ma0);
    cudaGetSymbolAddress((void**)&ma1, g_ma1);

    const int SMEM3 = 2 * 6 * 16384;   // 196608
    const int SMEM2 = 2 * 4 * 16384;   // 131072
    cudaFuncSetAttribute(gemm_hmma<3>, cudaFuncAttributeMaxDynamicSharedMemorySize, SMEM3);
    cudaFuncSetAttribute(gemm_hmma<2>, cudaFuncAttributeMaxDynamicSharedMemorySize, SMEM2);

    // 1) weights -> 3-way bf16 split (K-major [m][k])
    {
        long n = (long)C3 * KDIM;
        convert_split<3><<<(int)((n / 4 + 255) / 256), 256>>>(qkv_w, n, wq0, wq1, wq2);
    }
    // 2) x -> plain 3-way split, [k][n] layout
    {
        long n = (long)BB * CC * NPIX;
        convert_split<3><<<(int)((n / 4 + 255) / 256), 256>>>(x, n, xT0, xT1, xT2);
    }
    // 3) zero norm accumulators
    zero_norm<<<(BB * 2 * CC + 255) / 256, 256>>>(nrm);

    // 4) GEMM1-qk: rows 0..767 (topk-critical, 6 products) — persistent
    gemm_hmma<3><<<GPERS, 256, SMEM3>>>(
        wq0, wq1, wq2, xT0, xT1, xT2, qkv,
        0L, (long)CC * NPIX, (long)C3 * NPIX,
        6, 128, 6 * 128 * BB);

    // 5) GEMM1-v: rows 768..1151 (linear path, 3 products) — persistent
    gemm_hmma<2><<<GPERS, 256, SMEM2>>>(
        wq0 + (long)768 * KDIM, wq1 + (long)768 * KDIM, wq0,
        xT0, xT1, xT0, qkv + (long)768 * NPIX,
        0L, (long)CC * NPIX, (long)C3 * NPIX,
        3, 128, 3 * 128 * BB);

    // 6) depthwise 3x3: q,k -> fp32 + norms; v -> bf16 2-split [k][n]
    dwconv3x3_fused<<<dim3(HH / 8, BB * C3), 256>>>(qkv, dw_w, dw, nrm, vT0, vT1);

    gram_partial<<<dim3(BB * HEADS, NCHUNK), 64>>>(dw, spart);
    topk_softmax<<<(BB * HEADS * CH + 255) / 256, 256>>>(spart, nrm, temp, attn);
    combine_proj<<<dim3(BB * HEADS, 3), 256>>>(attn, projw, Mm);

    // M -> 2-way split (K-major [m][k])
    {
        long n = (long)BB * CC * CC;
        convert_split<2><<<(int)((n / 4 + 255) / 256), 256>>>(Mm, n, ma0, ma1, ma0);
    }

    // GEMM2: out = M_b @ v — persistent
    gemm_hmma<2><<<GPERS, 256, SMEM2>>>(
        ma0, ma1, ma0, vT0, vT1, vT0, out,
        (long)CC * CC, (long)CC * NPIX, (long)CC * NPIX,
        3, 128, 3 * 128 * BB);
}

// round 10
// speedup vs baseline: 1.0304x; 1.0304x over previous
#include <cuda_runtime.h>
#include <cuda_bf16.h>
#include <math.h>
#include <stdint.h>

// Problem constants
#define BB    8
#define CC    384
#define C3    1152
#define HH    128
#define WW    128
#define NPIX  16384
#define HEADS 8
#define CH    48
#define TOPK_ 7
#define NCHUNK  16
#define CHUNK_N 1024
#define KDIM  384
#define KCHUNKS 6          // 384 / 64

#define SMEM_SWIZZLE_128B(o) ((o) ^ (((o) >> 3) & 0x70))

// ---------------- scratch ---------------------------------------------------
__device__ float g_qkv[(long)BB * C3 * NPIX];
__device__ float g_dw [(long)BB * C3 * NPIX];     // only q,k region used
__device__ float g_norm[BB * 2 * CC];
__device__ float g_Spart[(long)NCHUNK * BB * HEADS * CH * CH];
__device__ float g_attn[BB * HEADS * CH * CH];
__device__ float g_M[BB * CC * CC];
// bf16 split operands, [k][n] layout (n contiguous, row stride NPIX)
__device__ __nv_bfloat16 g_xT0[(long)BB * CC * NPIX];
__device__ __nv_bfloat16 g_xT1[(long)BB * CC * NPIX];
__device__ __nv_bfloat16 g_xT2[(long)BB * CC * NPIX];
__device__ __nv_bfloat16 g_vT0[(long)BB * CC * NPIX];
__device__ __nv_bfloat16 g_vT1[(long)BB * CC * NPIX];
__device__ __nv_bfloat16 g_wq0[C3 * KDIM];
__device__ __nv_bfloat16 g_wq1[C3 * KDIM];
__device__ __nv_bfloat16 g_wq2[C3 * KDIM];
__device__ __nv_bfloat16 g_ma0[BB * CC * CC];
__device__ __nv_bfloat16 g_ma1[BB * CC * CC];

// ---------------- PTX helpers (base sm_103-compatible only) -----------------
__device__ __forceinline__ uint32_t smem_u32(const void* p) {
    uint32_t a;
    asm("{ .reg .u64 t; cvta.to.shared.u64 t, %1; cvt.u32.u64 %0, t; }"
        : "=r"(a) : "l"(p));
    return a;
}

#define CP_ASYNC16(dst, src) \
    asm volatile("cp.async.cg.shared.global [%0], [%1], 16;" :: "r"(dst), "l"(src))
#define CP_COMMIT()  asm volatile("cp.async.commit_group;")
#define CP_WAIT1()   asm volatile("cp.async.wait_group 1;")

#define LDSM_X4(r0, r1, r2, r3, addr) \
    asm volatile("ldmatrix.sync.aligned.m8n8.x4.shared.b16 {%0,%1,%2,%3}, [%4];" \
        : "=r"(r0), "=r"(r1), "=r"(r2), "=r"(r3) : "r"(addr))

#define LDSM_X4_T(r0, r1, r2, r3, addr) \
    asm volatile("ldmatrix.sync.aligned.m8n8.x4.trans.shared.b16 {%0,%1,%2,%3}, [%4];" \
        : "=r"(r0), "=r"(r1), "=r"(r2), "=r"(r3) : "r"(addr))

#define MMA16816(d, a, b0, b1) \
    asm volatile("mma.sync.aligned.m16n8k16.row.col.f32.bf16.bf16.f32 " \
        "{%0,%1,%2,%3}, {%4,%5,%6,%7}, {%8,%9}, {%0,%1,%2,%3};" \
        : "+f"((d)[0]), "+f"((d)[1]), "+f"((d)[2]), "+f"((d)[3]) \
        : "r"((a)[0]), "r"((a)[1]), "r"((a)[2]), "r"((a)[3]), "r"(b0), "r"(b1))

// ---------------- HMMA split-bf16 GEMM (R7 tiled form — best known) ---------
// D[m,n] = sum_k A[m,k]*B[k,n].
// A splits: [m][k] K-major rows (stride KDIM). B splits: [k][n] rows (stride NPIX).
// CTA tile 128x128, 8 warps of 64x32, K-chunks of 64, double-buffered cp.async.
template<int NSPLIT>
__global__ __launch_bounds__(256, 1)
void gemm_hmma(const __nv_bfloat16* __restrict__ A0, const __nv_bfloat16* __restrict__ A1,
               const __nv_bfloat16* __restrict__ A2,
               const __nv_bfloat16* __restrict__ B0, const __nv_bfloat16* __restrict__ B1,
               const __nv_bfloat16* __restrict__ B2,
               float* __restrict__ C,
               long aBatch, long bBatch, long cBatch)
{
    constexpr int NTILES = 2 * NSPLIT;
    constexpr int BUFB   = NTILES * 16384;
    extern __shared__ char smem[];
    const uint32_t sb = smem_u32(smem);
    const int tid  = threadIdx.x;
    const int wid  = tid >> 5, lane = tid & 31;
    const int m0 = blockIdx.x * 128, n0 = blockIdx.y * 128, bz = blockIdx.z;
    const int warp_m = (wid >> 2) * 64, warp_n = (wid & 3) * 32;

    const __nv_bfloat16* tbase[6];
    tbase[0] = A0 + bz * aBatch + (long)m0 * KDIM;
    tbase[1] = A1 + bz * aBatch + (long)m0 * KDIM;
    tbase[2] = A2 + bz * aBatch + (long)m0 * KDIM;
    tbase[NSPLIT + 0] = B0 + bz * bBatch + n0;
    tbase[NSPLIT + 1] = B1 + bz * bBatch + n0;
    tbase[NSPLIT + 2] = B2 + bz * bBatch + n0;

    uint32_t aoff[4][4];
    {
        const int arow = lane & 15, akh = lane >> 4;
#pragma unroll
        for (int ks = 0; ks < 4; ks++)
#pragma unroll
            for (int i = 0; i < 4; i++) {
                int o = (warp_m + i * 16 + arow) * 128 + (ks * 16 + akh * 8) * 2;
                aoff[i][ks] = SMEM_SWIZZLE_128B(o);
            }
    }
    uint32_t boff[2];
    {
        const int krow = (lane & 7) + (((lane >> 3) & 1) << 3);
        const int ncol = warp_n + ((lane >> 4) << 3);
        boff[0] = (uint32_t)((krow * 256 + ncol * 2) ^ ((krow & 7) << 4));
        boff[1] = (uint32_t)((krow * 256 + (ncol + 16) * 2) ^ ((krow & 7) << 4));
    }

    float acc[4][4][4];
#pragma unroll
    for (int i = 0; i < 4; i++)
#pragma unroll
        for (int j = 0; j < 4; j++)
#pragma unroll
            for (int r = 0; r < 4; r++) acc[i][j][r] = 0.f;

    auto load_chunk = [&](int chunk, int buf) {
        const uint32_t bufOff = sb + buf * BUFB;
        const int kOff = chunk * 64;
#pragma unroll
        for (int i = 0; i < NTILES * 4; i++) {
            const int t = tid + i * 256;
            const int tile = t >> 10;
            const int idx  = t & 1023;
            const __nv_bfloat16* gp;
            uint32_t so;
            if (tile < NSPLIT) {              // A: 128m x 64k, 128B rows
                const int r = idx >> 3, s = idx & 7;
                gp = tbase[tile] + (long)r * KDIM + kOff + s * 8;
                so = bufOff + tile * 16384 + SMEM_SWIZZLE_128B(r * 128 + s * 16);
            } else {                          // B: 64k x 128n, 256B rows
                const int r = idx >> 4, s = idx & 15;
                gp = tbase[tile] + (long)(kOff + r) * NPIX + s * 8;
                so = bufOff + tile * 16384 + ((r * 256 + s * 16) ^ ((r & 7) << 4));
            }
            CP_ASYNC16(so, gp);
        }
    };

    load_chunk(0, 0); CP_COMMIT();
    load_chunk(1, 1); CP_COMMIT();

    for (int chunk = 0; chunk < KCHUNKS; chunk++) {
        CP_WAIT1();
        __syncthreads();
        const uint32_t bufA = sb + (chunk & 1) * BUFB;
#pragma unroll
        for (int ks = 0; ks < 4; ks++) {
            uint32_t a[NSPLIT][4][4], b[NSPLIT][2][4];
#pragma unroll
            for (int ai = 0; ai < NSPLIT; ai++) {
                const uint32_t At = bufA + ai * 16384;
#pragma unroll
                for (int i = 0; i < 4; i++)
                    LDSM_X4(a[ai][i][0], a[ai][i][1], a[ai][i][2], a[ai][i][3],
                            At + aoff[i][ks]);
            }
#pragma unroll
            for (int bi = 0; bi < NSPLIT; bi++) {
                const uint32_t Bt = bufA + (NSPLIT + bi) * 16384 + ks * 4096;
#pragma unroll
                for (int q = 0; q < 2; q++)
                    LDSM_X4_T(b[bi][q][0], b[bi][q][1], b[bi][q][2], b[bi][q][3],
                              Bt + boff[q]);
            }
#pragma unroll
            for (int ai = 0; ai < NSPLIT; ai++)
#pragma unroll
                for (int bi = 0; bi < NSPLIT; bi++) {
                    if (ai + bi >= NSPLIT) continue;   // dropped higher-order terms
#pragma unroll
                    for (int i = 0; i < 4; i++)
#pragma unroll
                        for (int j = 0; j < 4; j++)
                            MMA16816(acc[i][j], a[ai][i],
                                     b[bi][j >> 1][(j & 1) * 2],
                                     b[bi][j >> 1][(j & 1) * 2 + 1]);
                }
        }
        __syncthreads();
        if (chunk + 2 < KCHUNKS) load_chunk(chunk + 2, chunk & 1);
        CP_COMMIT();
    }

    const int gid = lane >> 2, qd = lane & 3;
#pragma unroll
    for (int i = 0; i < 4; i++) {
        const int r0 = m0 + warp_m + i * 16 + gid;
        float* p0 = C + bz * cBatch + (long)r0 * NPIX + n0 + warp_n + qd * 2;
        float* p1 = p0 + 8L * NPIX;
#pragma unroll
        for (int j = 0; j < 4; j++) {
            *(float2*)(p0 + j * 8) = make_float2(acc[i][j][0], acc[i][j][1]);
            *(float2*)(p1 + j * 8) = make_float2(acc[i][j][2], acc[i][j][3]);
        }
    }
}

// ---------------- vectorized elementwise bf16 split (4 elems/thread) --------
template<int NSPLIT>
__global__ void convert_split(const float* __restrict__ in, long n,
                              __nv_bfloat16* __restrict__ o0,
                              __nv_bfloat16* __restrict__ o1,
                              __nv_bfloat16* __restrict__ o2)
{
    long i = ((long)blockIdx.x * blockDim.x + threadIdx.x) * 4;
    if (i >= n) return;
    float4 v = *(const float4*)(in + i);
    float vv[4] = {v.x, v.y, v.z, v.w};
    __nv_bfloat16 h0[4], h1[4], h2[4];
#pragma unroll
    for (int j = 0; j < 4; j++) {
        h0[j] = __float2bfloat16(vv[j]);
        float r1 = vv[j] - __bfloat162float(h0[j]);
        h1[j] = __float2bfloat16(r1);
        if (NSPLIT == 3) {
            float r2 = r1 - __bfloat162float(h1[j]);
            h2[j] = __float2bfloat16(r2);
        }
    }
    *(uint2*)(o0 + i) = *(uint2*)h0;
    *(uint2*)(o1 + i) = *(uint2*)h1;
    if (NSPLIT == 3) *(uint2*)(o2 + i) = *(uint2*)h2;
}

// ---------------- zero norm accumulator -------------------------------------
__global__ void zero_norm(float* __restrict__ nrm)
{
    int i = blockIdx.x * 256 + threadIdx.x;
    if (i < BB * 2 * CC) nrm[i] = 0.f;
}

// ---------------- fused depthwise 3x3 + norms + v bf16 split ----------------
__global__ __launch_bounds__(256)
void dwconv3x3_fused(const float* __restrict__ in,
                     const float* __restrict__ w,
                     float* __restrict__ out,
                     float* __restrict__ nrmsq,
                     __nv_bfloat16* __restrict__ vT0,
                     __nv_bfloat16* __restrict__ vT1)
{
    const int ch = blockIdx.y;                 // 0 .. BB*C3-1
    const int c  = ch % C3;
    const int b  = ch / C3;
    const int y0 = blockIdx.x * 8;
    const float* ip = in + (long)ch * NPIX;

    __shared__ float s[10][136];

    const int tid = threadIdx.x;
    const int r   = tid >> 5;
    const int l   = tid & 31;

#pragma unroll
    for (int j = r; j < 10; j += 8) {
        const int gy = y0 - 1 + j;
        float4 v = make_float4(0.f, 0.f, 0.f, 0.f);
        if (gy >= 0 && gy < HH) v = *(const float4*)(ip + gy * WW + l * 4);
        *(float4*)&s[j][4 + l * 4] = v;
        if (l == 0)  s[j][3]   = 0.f;
        if (l == 31) s[j][132] = 0.f;
    }

    float wv[9];
#pragma unroll
    for (int i = 0; i < 9; i++) wv[i] = w[c * 9 + i];
    __syncthreads();

    const int rseg = r >> 2;
    const int cseg = r & 3;
    const int col  = cseg * 32 + l;
    const int rb   = rseg * 4;

    float o[4] = {0.f, 0.f, 0.f, 0.f};
#pragma unroll
    for (int j = 0; j < 6; j++) {
        const float m0 = s[rb + j][3 + col];
        const float m1 = s[rb + j][4 + col];
        const float m2 = s[rb + j][5 + col];
#pragma unroll
        for (int i = 0; i < 4; i++) {
            const int d = j - i;
            if (d >= 0 && d < 3)
                o[i] += wv[d * 3 + 0] * m0 + wv[d * 3 + 1] * m1 + wv[d * 3 + 2] * m2;
        }
    }

    if (c < 2 * CC) {
        float* op = out + (long)ch * NPIX;
        float ss = 0.f;
#pragma unroll
        for (int i = 0; i < 4; i++) {
            op[(y0 + rseg * 4 + i) * WW + col] = o[i];
            ss += o[i] * o[i];
        }
#pragma unroll
        for (int off = 16; off > 0; off >>= 1)
            ss += __shfl_xor_sync(0xFFFFFFFFu, ss, off);
        if (l == 0) atomicAdd(&nrmsq[b * (2 * CC) + c], ss);
    } else {
        const long base = ((long)b * CC + (c - 2 * CC)) * NPIX;
#pragma unroll
        for (int i = 0; i < 4; i++) {
            const int pix = (y0 + rseg * 4 + i) * WW + col;
            const float v = o[i];
            __nv_bfloat16 h = __float2bfloat16(v);
            vT0[base + pix] = h;
            vT1[base + pix] = __float2bfloat16(v - __bfloat162float(h));
        }
    }
}

// ---------------- gram partials v2: 64 threads, 6x6 register tile -----------
__global__ __launch_bounds__(64)
void gram_partial(const float* __restrict__ dw, float* __restrict__ spart)
{
    const int bh    = blockIdx.x;
    const int chunk = blockIdx.y;
    const int b = bh / HEADS, h = bh % HEADS;

    const float* qbase = dw + ((long)b * C3 + h * CH) * NPIX + chunk * CHUNK_N;
    const float* kbase = dw + ((long)b * C3 + CC + h * CH) * NPIX + chunk * CHUNK_N;

    __shared__ float qs[CH][68];
    __shared__ float ks[CH][68];

    float acc[6][6];
#pragma unroll
    for (int i = 0; i < 6; i++)
#pragma unroll
        for (int j = 0; j < 6; j++) acc[i][j] = 0.f;

    const int tid = threadIdx.x;
    const int ti  = tid >> 3, tj = tid & 7;    // 8x8 thread grid

    for (int nn = 0; nn < CHUNK_N; nn += 64) {
#pragma unroll
        for (int l = 0; l < 12; l++) {
            int idx  = tid + l * 64;
            int row  = idx >> 4;
            int col4 = (idx & 15) * 4;
            *(float4*)&qs[row][col4] = *(const float4*)(qbase + (long)row * NPIX + nn + col4);
            *(float4*)&ks[row][col4] = *(const float4*)(kbase + (long)row * NPIX + nn + col4);
        }
        __syncthreads();
#pragma unroll 2
        for (int k = 0; k < 64; k += 2) {
            float2 rq[6], rk[6];
#pragma unroll
            for (int i = 0; i < 6; i++) rq[i] = *(const float2*)&qs[ti + 8 * i][k];
#pragma unroll
            for (int j = 0; j < 6; j++) rk[j] = *(const float2*)&ks[tj + 8 * j][k];
#pragma unroll
            for (int i = 0; i < 6; i++)
#pragma unroll
                for (int j = 0; j < 6; j++)
                    acc[i][j] += rq[i].x * rk[j].x + rq[i].y * rk[j].y;
        }
        __syncthreads();
    }

    float* sp = spart + ((long)chunk * (BB * HEADS) + bh) * (CH * CH);
#pragma unroll
    for (int i = 0; i < 6; i++)
#pragma unroll
        for (int j = 0; j < 6; j++)
            sp[(ti + 8 * i) * CH + (tj + 8 * j)] = acc[i][j];
}

// ---------------- top-7 + masked softmax ------------------------------------
__global__ void topk_softmax(const float* __restrict__ spart,
                             const float* __restrict__ nrmsq,
                             const float* __restrict__ temp,
                             float* __restrict__ attn)
{
    const int row = blockIdx.x * blockDim.x + threadIdx.x;
    if (row >= BB * HEADS * CH) return;
    const int c  = row % CH;
    const int bh = row / CH;
    const int h  = bh % HEADS, b = bh / HEADS;

    const float nq = fmaxf(sqrtf(nrmsq[b * 768 + h * CH + c]), 1e-12f);
    const float t  = temp[h];

    float w[CH];
    for (int d = 0; d < CH; d++) {
        float s = 0.f;
        for (int ck = 0; ck < NCHUNK; ck++)
            s += spart[((long)ck * (BB * HEADS) + bh) * (CH * CH) + c * CH + d];
        const float nk = fmaxf(sqrtf(nrmsq[b * 768 + CC + h * CH + d]), 1e-12f);
        w[d] = s / (nq * nk) * t;
    }

    bool sel[CH];
    for (int d = 0; d < CH; d++) sel[d] = false;
    float m = -INFINITY;
    for (int it = 0; it < TOPK_; it++) {
        int bi = 0; float bv = -INFINITY;
        for (int d = 0; d < CH; d++)
            if (!sel[d] && w[d] > bv) { bv = w[d]; bi = d; }
        sel[bi] = true;
        if (it == 0) m = bv;
    }

    float ssum = 0.f;
    float e[CH];
    for (int d = 0; d < CH; d++) {
        e[d] = sel[d] ? expf(w[d] - m) : 0.f;
        ssum += e[d];
    }
    const float inv = 1.f / ssum;
    float* ap = attn + ((long)bh * CH + c) * CH;
    for (int d = 0; d < CH; d++) ap[d] = e[d] * inv;
}

// ---------------- fold proj into attn ---------------------------------------
__global__ __launch_bounds__(256)
void combine_proj(const float* __restrict__ attn,
                  const float* __restrict__ projw,
                  float* __restrict__ Mo)
{
    const int bh = blockIdx.x;
    const int ot = blockIdx.y;
    const int b = bh / HEADS, h = bh % HEADS;

    __shared__ float as[CH][CH + 1];
    for (int l = threadIdx.x; l < CH * CH; l += 256)
        as[l / CH][l % CH] = attn[(long)bh * CH * CH + l];
    __syncthreads();

    for (int l = threadIdx.x; l < 128 * CH; l += 256) {
        const int ol = l / CH, d = l % CH;
        const int o  = ot * 128 + ol;
        const float* pw = projw + (long)o * CC + h * CH;
        float s = 0.f;
#pragma unroll
        for (int cc = 0; cc < CH; cc++) s += pw[cc] * as[cc][d];
        Mo[((long)b * CC + o) * CC + h * CH + d] = s;
    }
}

// ---------------- launcher ---------------------------------------------------
extern "C" void kernel_launch(void* const* d_in, const int* in_sizes, int n_in,
                              void* d_out, int out_size)
{
    const float* x     = (const float*)d_in[0];
    const float* qkv_w = (const float*)d_in[1];
    const float* dw_w  = (const float*)d_in[2];
    const float* projw = (const float*)d_in[3];
    const float* temp  = (const float*)d_in[4];
    float* out = (float*)d_out;

    float *qkv, *dw, *nrm, *spart, *attn, *Mm;
    cudaGetSymbolAddress((void**)&qkv,   g_qkv);
    cudaGetSymbolAddress((void**)&dw,    g_dw);
    cudaGetSymbolAddress((void**)&nrm,   g_norm);
    cudaGetSymbolAddress((void**)&spart, g_Spart);
    cudaGetSymbolAddress((void**)&attn,  g_attn);
    cudaGetSymbolAddress((void**)&Mm,    g_M);

    __nv_bfloat16 *xT0, *xT1, *xT2, *vT0, *vT1, *wq0, *wq1, *wq2, *ma0, *ma1;
    cudaGetSymbolAddress((void**)&xT0, g_xT0);
    cudaGetSymbolAddress((void**)&xT1, g_xT1);
    cudaGetSymbolAddress((void**)&xT2, g_xT2);
    cudaGetSymbolAddress((void**)&vT0, g_vT0);
    cudaGetSymbolAddress((void**)&vT1, g_vT1);
    cudaGetSymbolAddress((void**)&wq0, g_wq0);
    cudaGetSymbolAddress((void**)&wq1, g_wq1);
    cudaGetSymbolAddress((void**)&wq2, g_wq2);
    cudaGetSymbolAddress((void**)&ma0, g_ma0);
    cudaGetSymbolAddress((void**)&ma1, g_ma1);

    const int SMEM3 = 2 * 6 * 16384;   // 196608
    const int SMEM2 = 2 * 4 * 16384;   // 131072
    cudaFuncSetAttribute(gemm_hmma<3>, cudaFuncAttributeMaxDynamicSharedMemorySize, SMEM3);
    cudaFuncSetAttribute(gemm_hmma<2>, cudaFuncAttributeMaxDynamicSharedMemorySize, SMEM2);

    // 1) weights -> 3-way bf16 split (K-major [m][k])
    {
        long n = (long)C3 * KDIM;
        convert_split<3><<<(int)((n / 4 + 255) / 256), 256>>>(qkv_w, n, wq0, wq1, wq2);
    }
    // 2) x -> plain 3-way split, [k][n] layout
    {
        long n = (long)BB * CC * NPIX;
        convert_split<3><<<(int)((n / 4 + 255) / 256), 256>>>(x, n, xT0, xT1, xT2);
    }
    // 3) zero norm accumulators
    zero_norm<<<(BB * 2 * CC + 255) / 256, 256>>>(nrm);

    // 4) GEMM1-qk: rows 0..767 (topk-critical, 6 products)
    gemm_hmma<3><<<dim3(768 / 128, NPIX / 128, BB), 256, SMEM3>>>(
        wq0, wq1, wq2, xT0, xT1, xT2, qkv,
        0L, (long)CC * NPIX, (long)C3 * NPIX);

    // 5) GEMM1-v: rows 768..1151 (linear path, 3 products)
    gemm_hmma<2><<<dim3(384 / 128, NPIX / 128, BB), 256, SMEM2>>>(
        wq0 + (long)768 * KDIM, wq1 + (long)768 * KDIM, wq0,
        xT0, xT1, xT0, qkv + (long)768 * NPIX,
        0L, (long)CC * NPIX, (long)C3 * NPIX);

    // 6) depthwise 3x3: q,k -> fp32 + norms; v -> bf16 2-split [k][n]
    dwconv3x3_fused<<<dim3(HH / 8, BB * C3), 256>>>(qkv, dw_w, dw, nrm, vT0, vT1);

    gram_partial<<<dim3(BB * HEADS, NCHUNK), 64>>>(dw, spart);
    topk_softmax<<<(BB * HEADS * CH + 255) / 256, 256>>>(spart, nrm, temp, attn);
    combine_proj<<<dim3(BB * HEADS, 3), 256>>>(attn, projw, Mm);

    // M -> 2-way split (K-major [m][k])
    {
        long n = (long)BB * CC * CC;
        convert_split<2><<<(int)((n / 4 + 255) / 256), 256>>>(Mm, n, ma0, ma1, ma0);
    }

    // GEMM2: out = M_b @ v
    gemm_hmma<2><<<dim3(CC / 128, NPIX / 128, BB), 256, SMEM2>>>(
        ma0, ma1, ma0, vT0, vT1, vT0, out,
        (long)CC * CC, (long)CC * NPIX, (long)CC * NPIX);
}